// round 5
// baseline (speedup 1.0000x reference)
#include <cuda_runtime.h>

// out[r][c] = posenc(X[r]) . W[3*voxel_ids[p] + c],  r = row_ids[p]
//
// W repacked to g_Wr[voxel][3][64], columns permuted so each angle's (sin,cos)
// weights are adjacent; raw-x at 60..62, pad 63. 8-lane subgroup per point,
// 4 points/warp, LDG.128 weight loads, shfl reduction.
//
// This round: depth-2 software pipeline — at iter t issue ids[t+2] and
// X/W[t+1], compute t — to hide the two dependent L2 round-trips that made
// R2 latency-bound (issue=34%). One grid wave (3 CTAs/SM).

#define NUM_VOXELS 512
#define TPB 256
#define NBLOCKS 444   // 148 SMs * 3 CTAs -> exactly one wave at ~80 regs

__device__ float4 g_Wr[NUM_VOXELS * 48];   // [voxel][3][64] floats

__global__ void repack_kernel(const float* __restrict__ W)
{
    int idx = blockIdx.x * blockDim.x + threadIdx.x;   // over 512*192 floats
    if (idx >= NUM_VOXELS * 192) return;
    int v = idx / 192;
    int t = idx - v * 192;
    int c = t >> 6;          // 0..2
    int j = t & 63;          // 0..63
    float val = 0.0f;
    if (j < 60) {
        int a = j >> 1;      // angle 0..29
        int s = j & 1;       // 0=sin 1=cos
        int f = a / 3;
        int d = a - 3 * f;
        val = W[(3 * v + c) * 63 + (3 + 6 * f + 3 * s + d)];
    } else if (j < 63) {
        val = W[(3 * v + c) * 63 + (j - 60)];
    }
    ((float*)g_Wr)[idx] = val;
}

__global__ void __launch_bounds__(TPB)
voxel_linear_kernel(const float* __restrict__ X,
                    const int* __restrict__ row_ids,
                    const int* __restrict__ voxel_ids,
                    float* __restrict__ out,
                    int n, int T)
{
    const int lane = threadIdx.x & 31;
    const int warp = threadIdx.x >> 5;
    const int L    = lane & 7;
    const int sg   = lane >> 3;

    // Per-lane slot constants: slot s=2h+q covers angle a = 16h + 2L + q.
    float scl[4];
    int   dsel[4];
#pragma unroll
    for (int s = 0; s < 4; ++s) {
        int a = 16 * (s >> 1) + 2 * L + (s & 1);
        int f = a / 3;
        dsel[s] = a - 3 * f;
        scl[s]  = (float)(1 << f);
    }

    const int stride = NBLOCKS * 32;
    int p = blockIdx.x * 32 + warp * 4 + sg;   // point index for iteration t

    // ---- pipeline prologue ----
    // ids for t=0 and t=1
    bool act_cur = (p < n);
    int pp = act_cur ? p : 0;
    int r_cur = row_ids[pp];
    int v_cur = voxel_ids[pp];

    int p1 = p + stride;
    bool act_nxt = (p1 < n);
    pp = act_nxt ? p1 : 0;
    int r_nxt = row_ids[pp];
    int v_nxt = voxel_ids[pp];

    // X/W for t=0
    const float4* __restrict__ wr = g_Wr + v_cur * 48;
    float4 q00 = wr[     L], q01 = wr[ 8 + L];
    float4 q10 = wr[16 + L], q11 = wr[24 + L];
    float4 q20 = wr[32 + L], q21 = wr[40 + L];
    float x0 = X[3 * r_cur + 0];
    float x1 = X[3 * r_cur + 1];
    float x2 = X[3 * r_cur + 2];

    for (int t = 0; t < T; ++t) {
        // ---- issue ids for t+2 ----
        int p2 = p + 2 * stride;
        bool act2 = (p2 < n);
        int pp2 = act2 ? p2 : 0;
        int r2 = row_ids[pp2];
        int v2 = voxel_ids[pp2];

        // ---- issue X/W for t+1 ----
        const float4* __restrict__ wn = g_Wr + v_nxt * 48;
        float4 n00 = wn[     L], n01 = wn[ 8 + L];
        float4 n10 = wn[16 + L], n11 = wn[24 + L];
        float4 n20 = wn[32 + L], n21 = wn[40 + L];
        float nx0 = X[3 * r_nxt + 0];
        float nx1 = X[3 * r_nxt + 1];
        float nx2 = X[3 * r_nxt + 2];

        // ---- compute t (all operands already in registers) ----
        float e[8];
#pragma unroll
        for (int s = 0; s < 4; ++s) {
            float xv = (dsel[s] == 0) ? x0 : ((dsel[s] == 1) ? x1 : x2);
            __sincosf(xv * scl[s], &e[2 * s], &e[2 * s + 1]);
        }
        if (L == 7) { e[4] = x0; e[5] = x1; e[6] = x2; e[7] = 0.0f; }

        float a0, a1, a2;
        a0 = e[0]*q00.x; a0 = fmaf(e[1],q00.y,a0); a0 = fmaf(e[2],q00.z,a0); a0 = fmaf(e[3],q00.w,a0);
        a0 = fmaf(e[4],q01.x,a0); a0 = fmaf(e[5],q01.y,a0); a0 = fmaf(e[6],q01.z,a0); a0 = fmaf(e[7],q01.w,a0);
        a1 = e[0]*q10.x; a1 = fmaf(e[1],q10.y,a1); a1 = fmaf(e[2],q10.z,a1); a1 = fmaf(e[3],q10.w,a1);
        a1 = fmaf(e[4],q11.x,a1); a1 = fmaf(e[5],q11.y,a1); a1 = fmaf(e[6],q11.z,a1); a1 = fmaf(e[7],q11.w,a1);
        a2 = e[0]*q20.x; a2 = fmaf(e[1],q20.y,a2); a2 = fmaf(e[2],q20.z,a2); a2 = fmaf(e[3],q20.w,a2);
        a2 = fmaf(e[4],q21.x,a2); a2 = fmaf(e[5],q21.y,a2); a2 = fmaf(e[6],q21.z,a2); a2 = fmaf(e[7],q21.w,a2);

#pragma unroll
        for (int off = 4; off > 0; off >>= 1) {
            a0 += __shfl_down_sync(0xffffffffu, a0, off, 8);
            a1 += __shfl_down_sync(0xffffffffu, a1, off, 8);
            a2 += __shfl_down_sync(0xffffffffu, a2, off, 8);
        }

        if (L == 0 && act_cur) {
            out[3 * r_cur + 0] = a0;
            out[3 * r_cur + 1] = a1;
            out[3 * r_cur + 2] = a2;
        }

        // ---- rotate pipeline ----
        r_cur = r_nxt; v_cur = v_nxt; act_cur = act_nxt;
        r_nxt = r2;    v_nxt = v2;    act_nxt = act2;
        q00 = n00; q01 = n01; q10 = n10; q11 = n11; q20 = n20; q21 = n21;
        x0 = nx0; x1 = nx1; x2 = nx2;
        p += stride;
    }
}

extern "C" void kernel_launch(void* const* d_in, const int* in_sizes, int n_in,
                              void* d_out, int out_size)
{
    const float* X         = (const float*)d_in[0];
    const float* W         = (const float*)d_in[1];
    const int*   row_ids   = (const int*)d_in[2];
    const int*   voxel_ids = (const int*)d_in[3];
    float*       out       = (float*)d_out;

    const int n = in_sizes[0] / 3;          // N_POINTS
    const int nchunks = (n + 31) / 32;      // warp-iterations over all points
    const int T = (nchunks + NBLOCKS - 1) / NBLOCKS;

    repack_kernel<<<(NUM_VOXELS * 192 + 255) / 256, 256>>>(W);
    voxel_linear_kernel<<<NBLOCKS, TPB>>>(X, row_ids, voxel_ids, out, n, T);
}